// round 3
// baseline (speedup 1.0000x reference)
#include <cuda_runtime.h>

#define BB 32
#define OO 64
#define MM 128
#define HH 4
#define EE 64
#define HE 256
#define OB 8          // o's per block
#define EP 68         // padded ctx row stride (floats) -> LDS.128 conflict-free
#define EP4 17        // EP/4

__device__ __forceinline__ float tanh_approx(float x) {
    float r;
    asm("tanh.approx.f32 %0, %1;" : "=f"(r) : "f"(x));
    return r;
}

// smem layout (floats):
//  ctxS  [MM][EP]   = 8704   (padded, logits reads row-per-lane)
//  memS  [MM][EE]   = 8192   (unpadded, heads reads are j-contiguous)
//  qS    [OB][HE]   = 2048
//  wS    [EE]       = 64
//  qrowS [OB][EE]   = 512
//  probS [OB][HH*MM]= 4096   (logits -> probs in place; reused as redS in out-GEMM)
//  headsS[OB][HE]   = 2048
#define SMEM_FLOATS (MM*EP + MM*EE + OB*HE + EE + OB*EE + OB*HH*MM + OB*HE)

__global__ __launch_bounds__(512, 2) void attn_fused3_kernel(
    const float* __restrict__ query,   // [B,O,E]
    const float* __restrict__ context, // [B,M,E]
    const float* __restrict__ memory,  // [B,M,E]
    const float* __restrict__ W_ch,    // [E, HE]
    const float* __restrict__ b_ch,    // [HE]
    const float* __restrict__ w_logit, // [E]
    const float* __restrict__ b_logit, // [1]
    const float* __restrict__ W_rh,    // [HE, E]
    const float* __restrict__ b_rh,    // [E]
    const float* __restrict__ temp,    // [1]
    float* __restrict__ out)           // [B,O,E]
{
    extern __shared__ float smem[];
    float* ctxS   = smem;                      // [MM][EP]
    float* memS   = ctxS + MM * EP;            // [MM][EE] unpadded
    float* qS     = memS + MM * EE;            // [OB][HE]
    float* wS     = qS + OB * HE;              // [EE]
    float* qrowS  = wS + EE;                   // [OB][EE]
    float* probS  = qrowS + OB * EE;           // [OB][HH*MM]  (aliased as redS later)
    float* headsS = probS + OB * HH * MM;      // [OB][HE]

    float4* ctxS4 = (float4*)ctxS;
    float4* memS4 = (float4*)memS;

    const int t  = threadIdx.x;
    const int b  = blockIdx.x >> 3;            // / (OO/OB)
    const int o0 = (blockIdx.x & 7) * OB;

    const float4* ctxG4 = (const float4*)(context + (size_t)b * MM * EE);
    const float4* memG4 = (const float4*)(memory  + (size_t)b * MM * EE);

    // ---- stage context (padded) & memory (unpadded) ----
    #pragma unroll
    for (int i = t; i < MM * EE / 4; i += 512) {
        int m = i >> 4, j = i & 15;
        ctxS4[m * EP4 + j] = ctxG4[i];
        memS4[i]           = memG4[i];
    }
    if (t < EE) wS[t] = w_logit[t];
    {   // qrowS[o][e], all 512 threads
        int o = t >> 6, e = t & 63;
        qrowS[t] = query[(size_t)(b * OO + o0 + o) * EE + e];
    }
    __syncthreads();

    // ---- q projection: thread=(grp,col), 4 o-accumulators each ----
    {
        const int col = t & 255;
        const int grp = t >> 8;                // 0/1 -> o range grp*4..grp*4+3
        const float* qr = qrowS + grp * 4 * EE;
        float bc = b_ch[col];
        float a0 = bc, a1 = bc, a2 = bc, a3 = bc;
        #pragma unroll 8
        for (int k = 0; k < EE; k++) {
            float w = W_ch[k * HE + col];
            a0 = fmaf(qr[k],           w, a0);
            a1 = fmaf(qr[EE + k],      w, a1);
            a2 = fmaf(qr[2 * EE + k],  w, a2);
            a3 = fmaf(qr[3 * EE + k],  w, a3);
        }
        float* qd = qS + grp * 4 * HE + col;
        qd[0]      = a0;
        qd[HE]     = a1;
        qd[2 * HE] = a2;
        qd[3 * HE] = a3;
    }
    __syncthreads();

    // ---- logits: thread=(h,m); two passes of 4 o's ----
    const float invtemp = 1.0f / temp[0];
    const float blog    = b_logit[0];
    {
        const int h = t >> 7;                  // warp-uniform
        const int m = t & 127;
        const float4* cr4 = ctxS4 + m * EP4;   // conflict-free LDS.128
        const float4* w4p = (const float4*)wS; // broadcast
        #pragma unroll
        for (int og = 0; og < 2; og++) {
            const float4* q0p = (const float4*)(qS + (og * 4 + 0) * HE) + h * 16;
            const float4* q1p = (const float4*)(qS + (og * 4 + 1) * HE) + h * 16;
            const float4* q2p = (const float4*)(qS + (og * 4 + 2) * HE) + h * 16;
            const float4* q3p = (const float4*)(qS + (og * 4 + 3) * HE) + h * 16;
            float a0 = 0.f, a1 = 0.f, a2 = 0.f, a3 = 0.f;
            #pragma unroll
            for (int j = 0; j < 16; j++) {
                float4 w4 = w4p[j];
                float4 c4 = cr4[j];
                float4 q0 = q0p[j], q1 = q1p[j], q2 = q2p[j], q3 = q3p[j];
                a0 = fmaf(w4.x, tanh_approx(c4.x + q0.x), a0);
                a1 = fmaf(w4.x, tanh_approx(c4.x + q1.x), a1);
                a2 = fmaf(w4.x, tanh_approx(c4.x + q2.x), a2);
                a3 = fmaf(w4.x, tanh_approx(c4.x + q3.x), a3);
                a0 = fmaf(w4.y, tanh_approx(c4.y + q0.y), a0);
                a1 = fmaf(w4.y, tanh_approx(c4.y + q1.y), a1);
                a2 = fmaf(w4.y, tanh_approx(c4.y + q2.y), a2);
                a3 = fmaf(w4.y, tanh_approx(c4.y + q3.y), a3);
                a0 = fmaf(w4.z, tanh_approx(c4.z + q0.z), a0);
                a1 = fmaf(w4.z, tanh_approx(c4.z + q1.z), a1);
                a2 = fmaf(w4.z, tanh_approx(c4.z + q2.z), a2);
                a3 = fmaf(w4.z, tanh_approx(c4.z + q3.z), a3);
                a0 = fmaf(w4.w, tanh_approx(c4.w + q0.w), a0);
                a1 = fmaf(w4.w, tanh_approx(c4.w + q1.w), a1);
                a2 = fmaf(w4.w, tanh_approx(c4.w + q2.w), a2);
                a3 = fmaf(w4.w, tanh_approx(c4.w + q3.w), a3);
            }
            float* pd = probS + og * 4 * HH * MM + h * MM + m;
            pd[0]           = (a0 + blog) * invtemp;
            pd[HH * MM]     = (a1 + blog) * invtemp;
            pd[2 * HH * MM] = (a2 + blog) * invtemp;
            pd[3 * HH * MM] = (a3 + blog) * invtemp;
        }
    }
    __syncthreads();

    // ---- softmax over m: 16 warps, each handles 2 (o,h) pairs ----
    {
        const int warp = t >> 5, lane = t & 31;
        #pragma unroll
        for (int p = warp; p < OB * HH; p += 16) {
            float* L = probS + (p >> 2) * (HH * MM) + (p & 3) * MM;
            float v0 = L[lane], v1 = L[lane + 32], v2 = L[lane + 64], v3 = L[lane + 96];
            float mx = fmaxf(fmaxf(v0, v1), fmaxf(v2, v3));
            #pragma unroll
            for (int s = 16; s; s >>= 1)
                mx = fmaxf(mx, __shfl_xor_sync(0xFFFFFFFFu, mx, s));
            float e0 = __expf(v0 - mx), e1 = __expf(v1 - mx);
            float e2 = __expf(v2 - mx), e3 = __expf(v3 - mx);
            float sm = e0 + e1 + e2 + e3;
            #pragma unroll
            for (int s = 16; s; s >>= 1)
                sm += __shfl_xor_sync(0xFFFFFFFFu, sm, s);
            float inv = 1.0f / sm;
            L[lane]      = e0 * inv; L[lane + 32] = e1 * inv;
            L[lane + 64] = e2 * inv; L[lane + 96] = e3 * inv;
        }
    }
    __syncthreads();

    // ---- heads: thread=(o,h,j) covers all 512 outputs, full m loop ----
    {
        const int o = t >> 6;
        const int h = (t >> 4) & 3;
        const int j = t & 15;
        const float*  pr  = probS + o * (HH * MM) + h * MM;
        const float4* mm4 = memS4 + j;
        float4 acc = make_float4(0.f, 0.f, 0.f, 0.f);
        #pragma unroll 8
        for (int m = 0; m < MM; m++) {
            float  p = pr[m];
            float4 v = mm4[m * 16];
            acc.x = fmaf(p, v.x, acc.x);
            acc.y = fmaf(p, v.y, acc.y);
            acc.z = fmaf(p, v.z, acc.z);
            acc.w = fmaf(p, v.w, acc.w);
        }
        float4 hd;
        hd.x = (acc.x > 0.f) ? acc.x : 0.01f * acc.x;
        hd.y = (acc.y > 0.f) ? acc.y : 0.01f * acc.y;
        hd.z = (acc.z > 0.f) ? acc.z : 0.01f * acc.z;
        hd.w = (acc.w > 0.f) ? acc.w : 0.01f * acc.w;
        ((float4*)headsS)[t] = hd;             // headsS[o][h*64 + 4j + c]
    }
    __syncthreads();

    // ---- out GEMM: thread=(part,e), W_rh read once per block, 8 o-accums ----
    float* redS = probS;                        // reuse [8][512]
    {
        const int part = t >> 6;               // 0..7, k range part*32..+31
        const int e    = t & 63;
        const float* wr = W_rh + (part * 32) * EE + e;
        const float* hs = headsS + part * 32;
        float a0=0.f,a1=0.f,a2=0.f,a3=0.f,a4=0.f,a5=0.f,a6=0.f,a7=0.f;
        #pragma unroll 4
        for (int k = 0; k < 32; k++) {
            float w = wr[k * EE];
            a0 = fmaf(hs[0 * HE + k], w, a0);
            a1 = fmaf(hs[1 * HE + k], w, a1);
            a2 = fmaf(hs[2 * HE + k], w, a2);
            a3 = fmaf(hs[3 * HE + k], w, a3);
            a4 = fmaf(hs[4 * HE + k], w, a4);
            a5 = fmaf(hs[5 * HE + k], w, a5);
            a6 = fmaf(hs[6 * HE + k], w, a6);
            a7 = fmaf(hs[7 * HE + k], w, a7);
        }
        float* rd = redS + part * 512 + e;
        rd[0]       = a0; rd[64]      = a1; rd[128] = a2; rd[192] = a3;
        rd[256]     = a4; rd[320]     = a5; rd[384] = a6; rd[448] = a7;
    }
    __syncthreads();
    {
        const int o = t >> 6, e = t & 63;
        float v = b_rh[e];
        #pragma unroll
        for (int p = 0; p < 8; p++)
            v += redS[p * 512 + t];
        out[(size_t)(b * OO + o0 + o) * EE + e] = v;
    }
}

extern "C" void kernel_launch(void* const* d_in, const int* in_sizes, int n_in,
                              void* d_out, int out_size) {
    const float* query   = (const float*)d_in[0];
    const float* context = (const float*)d_in[1];
    const float* memory  = (const float*)d_in[2];
    const float* W_ch    = (const float*)d_in[3];
    const float* b_ch    = (const float*)d_in[4];
    const float* w_logit = (const float*)d_in[5];
    const float* b_logit = (const float*)d_in[6];
    const float* W_rh    = (const float*)d_in[7];
    const float* b_rh    = (const float*)d_in[8];
    const float* temp    = (const float*)d_in[9];
    float* out = (float*)d_out;

    const size_t smem_bytes = SMEM_FLOATS * sizeof(float);
    cudaFuncSetAttribute(attn_fused3_kernel,
                         cudaFuncAttributeMaxDynamicSharedMemorySize,
                         (int)smem_bytes);

    attn_fused3_kernel<<<BB * (OO / OB), 512, smem_bytes>>>(
        query, context, memory, W_ch, b_ch, w_logit, b_logit, W_rh, b_rh, temp, out);
}

// round 7
// speedup vs baseline: 1.4891x; 1.4891x over previous
#include <cuda_runtime.h>

#define BB 32
#define OO 64
#define MM 128
#define HH 4
#define EE 64
#define HE 256
#define OBA 16        // o's per block, both kernels
#define EP 68         // padded ctx row stride (floats) -> LDS.128 conflict-free
#define EP4 17        // EP/4

// scratch: raw logits [b][o][h][m] (4 MB)
__device__ float g_logits[(size_t)BB * OO * HH * MM];

__device__ __forceinline__ float tanh_approx(float x) {
    float r;
    asm("tanh.approx.f32 %0, %1;" : "=f"(r) : "f"(x));
    return r;
}

// ===================== Kernel A: q-proj + logits (MUFU-bound) =====================
// grid = 128 (b, og16), block = 512
// smem: ctxS[MM][EP]=8704 | qS[OBA][HE]=4096 | wS[EE]=64 | qrowS[OBA][EE]=1024
#define SMEM_A_FLOATS (MM*EP + OBA*HE + EE + OBA*EE)

__global__ __launch_bounds__(512, 1) void attnA_logits_kernel(
    const float* __restrict__ query,   // [B,O,E]
    const float* __restrict__ context, // [B,M,E]
    const float* __restrict__ W_ch,    // [E, HE]
    const float* __restrict__ b_ch,    // [HE]
    const float* __restrict__ w_logit) // [E]
{
    extern __shared__ float smem[];
    float* ctxS  = smem;                    // [MM][EP]
    float* qS    = ctxS + MM * EP;          // [OBA][HE]
    float* wS    = qS + OBA * HE;           // [EE]
    float* qrowS = wS + EE;                 // [OBA][EE]
    float4* ctxS4 = (float4*)ctxS;

    const int t  = threadIdx.x;
    const int b  = blockIdx.x >> 2;
    const int o0 = (blockIdx.x & 3) * OBA;

    // ---- stage ----
    const float4* ctxG4 = (const float4*)(context + (size_t)b * MM * EE);
    #pragma unroll
    for (int i = t; i < MM * EE / 4; i += 512) {
        int m = i >> 4, j = i & 15;
        ctxS4[m * EP4 + j] = ctxG4[i];
    }
    if (t < EE) wS[t] = w_logit[t];
    #pragma unroll
    for (int i = t; i < OBA * EE; i += 512)
        qrowS[i] = query[(size_t)(b * OO + o0) * EE + i];
    __syncthreads();

    // ---- q projection: thread=(grp,col), 8 o-accumulators ----
    {
        const int col = t & 255;
        const int grp = t >> 8;               // 0/1 -> o range grp*8..+7
        const float* qr = qrowS + grp * 8 * EE;
        float acc[8];
        float bc = b_ch[col];
        #pragma unroll
        for (int i = 0; i < 8; i++) acc[i] = bc;
        #pragma unroll 8
        for (int k = 0; k < EE; k++) {
            float w = W_ch[k * HE + col];
            #pragma unroll
            for (int i = 0; i < 8; i++)
                acc[i] = fmaf(qr[i * EE + k], w, acc[i]);
        }
        #pragma unroll
        for (int i = 0; i < 8; i++)
            qS[(grp * 8 + i) * HE + col] = acc[i];
    }
    __syncthreads();

    // ---- logits: thread=(h,m); 4 passes of 4 o's; raw logits to global ----
    {
        const int h = t >> 7;                 // warp-uniform
        const int m = t & 127;
        const float4* cr4 = ctxS4 + m * EP4;  // conflict-free LDS.128
        const float4* w4p = (const float4*)wS;
        float* gout = g_logits + (((size_t)(b * OO + o0) * HH + h) * MM) + m;
        const size_t ostride = (size_t)HH * MM;
        #pragma unroll
        for (int og = 0; og < 4; og++) {
            const float4* q0p = (const float4*)(qS + (og * 4 + 0) * HE) + h * 16;
            const float4* q1p = (const float4*)(qS + (og * 4 + 1) * HE) + h * 16;
            const float4* q2p = (const float4*)(qS + (og * 4 + 2) * HE) + h * 16;
            const float4* q3p = (const float4*)(qS + (og * 4 + 3) * HE) + h * 16;
            float a0 = 0.f, a1 = 0.f, a2 = 0.f, a3 = 0.f;
            #pragma unroll
            for (int j = 0; j < 16; j++) {
                float4 w4 = w4p[j];
                float4 c4 = cr4[j];
                float4 q0 = q0p[j], q1 = q1p[j], q2 = q2p[j], q3 = q3p[j];
                a0 = fmaf(w4.x, tanh_approx(c4.x + q0.x), a0);
                a1 = fmaf(w4.x, tanh_approx(c4.x + q1.x), a1);
                a2 = fmaf(w4.x, tanh_approx(c4.x + q2.x), a2);
                a3 = fmaf(w4.x, tanh_approx(c4.x + q3.x), a3);
                a0 = fmaf(w4.y, tanh_approx(c4.y + q0.y), a0);
                a1 = fmaf(w4.y, tanh_approx(c4.y + q1.y), a1);
                a2 = fmaf(w4.y, tanh_approx(c4.y + q2.y), a2);
                a3 = fmaf(w4.y, tanh_approx(c4.y + q3.y), a3);
                a0 = fmaf(w4.z, tanh_approx(c4.z + q0.z), a0);
                a1 = fmaf(w4.z, tanh_approx(c4.z + q1.z), a1);
                a2 = fmaf(w4.z, tanh_approx(c4.z + q2.z), a2);
                a3 = fmaf(w4.z, tanh_approx(c4.z + q3.z), a3);
                a0 = fmaf(w4.w, tanh_approx(c4.w + q0.w), a0);
                a1 = fmaf(w4.w, tanh_approx(c4.w + q1.w), a1);
                a2 = fmaf(w4.w, tanh_approx(c4.w + q2.w), a2);
                a3 = fmaf(w4.w, tanh_approx(c4.w + q3.w), a3);
            }
            gout[(og * 4 + 0) * ostride] = a0;
            gout[(og * 4 + 1) * ostride] = a1;
            gout[(og * 4 + 2) * ostride] = a2;
            gout[(og * 4 + 3) * ostride] = a3;
        }
    }
}

// ===================== Kernel B: softmax + heads + out GEMM (FMA-bound) ============
// grid = 128 (b, og16), block = 512
// smem: memS[MM][EE]=8192 | probS[64][MM]=8192 | headsS[64*EE]=4096
#define SMEM_B_FLOATS (MM*EE + 64*MM + 64*EE)

__global__ __launch_bounds__(512, 1) void attnB_out_kernel(
    const float* __restrict__ memory,  // [B,M,E]
    const float* __restrict__ b_logit, // [1] (unused: cancels in softmax)
    const float* __restrict__ W_rh,    // [HE, E]
    const float* __restrict__ b_rh,    // [E]
    const float* __restrict__ temp,    // [1]
    float* __restrict__ out)           // [B,O,E]
{
    extern __shared__ float smem[];
    float* memS   = smem;                  // [MM][EE]
    float* probS  = memS + MM * EE;        // [64 rows][MM]
    float* headsS = probS + 64 * MM;       // [64 rows][EE] flat: row*64+e
    float4* memS4 = (float4*)memS;
    (void)b_logit;

    const int t  = threadIdx.x;
    const int b  = blockIdx.x >> 2;
    const int o0 = (blockIdx.x & 3) * OBA;

    // ---- stage memory tile ----
    const float4* memG4 = (const float4*)(memory + (size_t)b * MM * EE);
    #pragma unroll
    for (int i = t; i < MM * EE / 4; i += 512)
        memS4[i] = memG4[i];

    // ---- softmax: 16 warps x 4 rows; row = o_local*4 + h ----
    {
        const float invtemp = 1.0f / temp[0];
        const int warp = t >> 5, lane = t & 31;
        #pragma unroll
        for (int rr = 0; rr < 4; rr++) {
            const int r = warp * 4 + rr;
            const int ol = r >> 2, h = r & 3;
            const float4* lg = (const float4*)(g_logits +
                (((size_t)(b * OO + o0 + ol) * HH + h) * MM));
            float4 v = lg[lane];
            float mx = fmaxf(fmaxf(v.x, v.y), fmaxf(v.z, v.w));
            #pragma unroll
            for (int s = 16; s; s >>= 1)
                mx = fmaxf(mx, __shfl_xor_sync(0xFFFFFFFFu, mx, s));
            float e0 = __expf((v.x - mx) * invtemp);
            float e1 = __expf((v.y - mx) * invtemp);
            float e2 = __expf((v.z - mx) * invtemp);
            float e3 = __expf((v.w - mx) * invtemp);
            float sm = e0 + e1 + e2 + e3;
            #pragma unroll
            for (int s = 16; s; s >>= 1)
                sm += __shfl_xor_sync(0xFFFFFFFFu, sm, s);
            float inv = 1.0f / sm;
            float4 p = make_float4(e0 * inv, e1 * inv, e2 * inv, e3 * inv);
            ((float4*)(probS + r * MM))[lane] = p;
        }
    }
    __syncthreads();

    // ---- heads GEMM: 64 rows x 64 cols; thread tile = 2 rows x float4 ----
    {
        const int rt = t >> 4;                // 0..31 -> rows rt*2, rt*2+1
        const int ct = t & 15;                // float4 column
        const int r0 = rt * 2, r1 = r0 + 1;
        const float* p0 = probS + r0 * MM;
        const float* p1 = probS + r1 * MM;
        const float4* mv = memS4 + ct;
        float4 A0 = make_float4(0.f, 0.f, 0.f, 0.f);
        float4 A1 = make_float4(0.f, 0.f, 0.f, 0.f);
        #pragma unroll 4
        for (int m = 0; m < MM; m++) {
            float4 v = mv[m * 16];
            float a = p0[m], c = p1[m];
            A0.x = fmaf(a, v.x, A0.x); A0.y = fmaf(a, v.y, A0.y);
            A0.z = fmaf(a, v.z, A0.z); A0.w = fmaf(a, v.w, A0.w);
            A1.x = fmaf(c, v.x, A1.x); A1.y = fmaf(c, v.y, A1.y);
            A1.z = fmaf(c, v.z, A1.z); A1.w = fmaf(c, v.w, A1.w);
        }
        float4 H0, H1;
        H0.x = (A0.x > 0.f) ? A0.x : 0.01f * A0.x;
        H0.y = (A0.y > 0.f) ? A0.y : 0.01f * A0.y;
        H0.z = (A0.z > 0.f) ? A0.z : 0.01f * A0.z;
        H0.w = (A0.w > 0.f) ? A0.w : 0.01f * A0.w;
        H1.x = (A1.x > 0.f) ? A1.x : 0.01f * A1.x;
        H1.y = (A1.y > 0.f) ? A1.y : 0.01f * A1.y;
        H1.z = (A1.z > 0.f) ? A1.z : 0.01f * A1.z;
        H1.w = (A1.w > 0.f) ? A1.w : 0.01f * A1.w;
        ((float4*)(headsS + r0 * EE))[ct] = H0;
        ((float4*)(headsS + r1 * EE))[ct] = H1;
    }
    __syncthreads();

    // ---- out GEMM: heads[o](flat 256) @ W_rh; thread=(og2,e), 2 o's each ----
    {
        const int e   = t & 63;
        const int og2 = t >> 6;               // 0..7 -> o_local og2 and og2+8
        const float* wr = W_rh + e;
        const float* h0 = headsS + og2 * 256;        // heads flat: o*256 + k
        const float* h1 = headsS + (og2 + 8) * 256;
        float acc0 = 0.f, acc1 = 0.f;
        #pragma unroll 16
        for (int k = 0; k < HE; k++) {
            float w = wr[k * EE];
            acc0 = fmaf(h0[k], w, acc0);      // warp-uniform smem broadcast
            acc1 = fmaf(h1[k], w, acc1);
        }
        float br = b_rh[e];
        out[(size_t)(b * OO + o0 + og2) * EE + e]     = acc0 + br;
        out[(size_t)(b * OO + o0 + og2 + 8) * EE + e] = acc1 + br;
    }
}

extern "C" void kernel_launch(void* const* d_in, const int* in_sizes, int n_in,
                              void* d_out, int out_size) {
    const float* query   = (const float*)d_in[0];
    const float* context = (const float*)d_in[1];
    const float* memory  = (const float*)d_in[2];
    const float* W_ch    = (const float*)d_in[3];
    const float* b_ch    = (const float*)d_in[4];
    const float* w_logit = (const float*)d_in[5];
    const float* b_logit = (const float*)d_in[6];
    const float* W_rh    = (const float*)d_in[7];
    const float* b_rh    = (const float*)d_in[8];
    const float* temp    = (const float*)d_in[9];
    float* out = (float*)d_out;

    const size_t smemA = SMEM_A_FLOATS * sizeof(float);
    const size_t smemB = SMEM_B_FLOATS * sizeof(float);
    cudaFuncSetAttribute(attnA_logits_kernel,
                         cudaFuncAttributeMaxDynamicSharedMemorySize, (int)smemA);
    cudaFuncSetAttribute(attnB_out_kernel,
                         cudaFuncAttributeMaxDynamicSharedMemorySize, (int)smemB);

    attnA_logits_kernel<<<BB * (OO / OBA), 512, smemA>>>(
        query, context, W_ch, b_ch, w_logit);
    attnB_out_kernel<<<BB * (OO / OBA), 512, smemB>>>(
        memory, b_logit, W_rh, b_rh, temp, out);
}